// round 4
// baseline (speedup 1.0000x reference)
#include <cuda_runtime.h>
#include <cuda_bf16.h>

#define BS 131072
#define PLEN 10
#define NCH1 23   // K1 = 361 padded to 368 = 23 chunks of 16

// -------- pre-split weights: packed bf16 (2 per u32 along k), hi & lo parts --------
__device__ __align__(16) unsigned g_W1h[NCH1 * 256 * 8], g_W1l[NCH1 * 256 * 8]; // [kc][n][8]
__device__ __align__(16) unsigned g_W2h[4 * 128 * 32],   g_W2l[4 * 128 * 32];   // [kc][n][32]
__device__ __align__(16) unsigned g_W3h[64 * 64],        g_W3l[64 * 64];        // [n][64]
__device__ __align__(16) unsigned g_Whh[192 * 32],       g_Whl[192 * 32];       // [n][32]

// ---------------------------------------------------------------------------
__device__ __forceinline__ unsigned packbf(float lo, float hi) {
    unsigned r;
    asm("cvt.rn.bf16x2.f32 %0, %1, %2;" : "=r"(r) : "f"(hi), "f"(lo));
    return r;
}
// v0 -> low half, v1 -> high half; hi = bf16 round, lo = bf16(residual)
__device__ __forceinline__ void split2(float v0, float v1, unsigned& hi, unsigned& lo) {
    hi = packbf(v0, v1);
    float h0 = __uint_as_float(hi << 16);
    float h1 = __uint_as_float(hi & 0xffff0000u);
    lo = packbf(v0 - h0, v1 - h1);
}
__device__ __forceinline__ float relu_(float v) { return v > 0.f ? v : 0.f; }

__device__ __forceinline__ void mma16(float* c, const unsigned* a, unsigned b0, unsigned b1) {
    asm("mma.sync.aligned.m16n8k16.row.col.f32.bf16.bf16.f32 "
        "{%0,%1,%2,%3},{%4,%5,%6,%7},{%8,%9},{%0,%1,%2,%3};"
        : "+f"(c[0]), "+f"(c[1]), "+f"(c[2]), "+f"(c[3])
        : "r"(a[0]), "r"(a[1]), "r"(a[2]), "r"(a[3]), "r"(b0), "r"(b1));
}

__device__ __forceinline__ void cpa4(void* s, const void* g) {
    unsigned a = (unsigned)__cvta_generic_to_shared(s);
    asm volatile("cp.async.ca.shared.global [%0],[%1],4;" :: "r"(a), "l"(g));
}
__device__ __forceinline__ void cpa16(void* s, const void* g) {
    unsigned a = (unsigned)__cvta_generic_to_shared(s);
    asm volatile("cp.async.cg.shared.global [%0],[%1],16;" :: "r"(a), "l"(g));
}
__device__ __forceinline__ void cp_commit() { asm volatile("cp.async.commit_group;"); }
template <int N>
__device__ __forceinline__ void cp_wait() { asm volatile("cp.async.wait_group %0;" :: "n"(N)); }

// load fp32 A tile fragment (16 rows) and split to bf16 hi/lo frags
__device__ __forceinline__ void ldA_f32(const float* base, int stride, int g, int tg,
                                        unsigned* Ah, unsigned* Al) {
    float2 p0 = *(const float2*)(base + g * stride + 2 * tg);
    float2 p1 = *(const float2*)(base + (g + 8) * stride + 2 * tg);
    float2 p2 = *(const float2*)(base + g * stride + 2 * tg + 8);
    float2 p3 = *(const float2*)(base + (g + 8) * stride + 2 * tg + 8);
    split2(p0.x, p0.y, Ah[0], Al[0]);
    split2(p1.x, p1.y, Ah[1], Al[1]);
    split2(p2.x, p2.y, Ah[2], Al[2]);
    split2(p3.x, p3.y, Ah[3], Al[3]);
}

// ---------------------------------------------------------------------------
// prep kernel: fp32 weights -> packed bf16 hi/lo global scratch
// ---------------------------------------------------------------------------
__global__ void prep_kernel(const float* __restrict__ W1, const float* __restrict__ W2,
                            const float* __restrict__ W3, const float* __restrict__ Whh) {
    int i = blockIdx.x * 256 + threadIdx.x;
    const int N1 = NCH1 * 256 * 8, N2 = 4 * 128 * 32, N3 = 64 * 64, N4 = 192 * 32;
    if (i < N1) {
        int kc = i / 2048, rem = i % 2048, n = rem >> 3, u = rem & 7;
        int k = kc * 16 + 2 * u;
        float v0 = (k < 361)     ? W1[n * 361 + k]     : 0.f;
        float v1 = (k + 1 < 361) ? W1[n * 361 + k + 1] : 0.f;
        split2(v0, v1, g_W1h[i], g_W1l[i]);
    } else if (i < N1 + N2) {
        int j = i - N1;
        int kc = j / 4096, rem = j % 4096, n = rem >> 5, u = rem & 31;
        int k = kc * 64 + 2 * u;
        split2(W2[n * 256 + k], W2[n * 256 + k + 1], g_W2h[j], g_W2l[j]);
    } else if (i < N1 + N2 + N3) {
        int j = i - N1 - N2;
        int n = j >> 6, u = j & 63, k = 2 * u;
        split2(W3[n * 128 + k], W3[n * 128 + k + 1], g_W3h[j], g_W3l[j]);
    } else if (i < N1 + N2 + N3 + N4) {
        int j = i - N1 - N2 - N3;
        int n = j >> 5, u = j & 31, k = 2 * u;
        split2(Whh[n * 64 + k], Whh[n * 64 + k + 1], g_Whh[j], g_Whl[j]);
    }
}

// ---------------------------------------------------------------------------
// fused kernel: MLP (3 GEMMs) + GRU (10 steps), 128 rows per CTA, 512 threads.
// smem offsets (4-byte units), peak 52224 = 208896 B:
//  h1_hi [128][132] @0, h1_lo @16896                          (..33792)
//  P1: zbuf 2x[128][20] @33792, w1h 2x[256][12] @38912, w1l @45056  (..51200)
//  P2: w2h 2x[128][36] @33792, w2l @43008                     (..52224)
//  P3: h fp32 [128][68] @0, w3h [64][68] @8704, w3l @13056,
//      h2_hi [128][68] @33792, h2_lo @42496                   (..51200)
//  GRU: h @0, gh [128][196] @8704, whh_h [192][36] @33792, whh_l @40704,
//       wih @47616, bih @48000, bhh @48192, wo @48384, bo @48512,
//       x @48516, xh [128][20] @48772                         (..51332)
// ---------------------------------------------------------------------------
__global__ void __launch_bounds__(512, 1) fused_kernel(
    const float* __restrict__ z,
    const float* __restrict__ b1, const float* __restrict__ b2, const float* __restrict__ b3,
    const float* __restrict__ Wih, const float* __restrict__ bih, const float* __restrict__ bhh,
    const float* __restrict__ Wo, const float* __restrict__ bo,
    float* __restrict__ out)
{
    extern __shared__ float sm[];
    unsigned* smu = (unsigned*)sm;

    const int tid = threadIdx.x, lane = tid & 31, wid = tid >> 5;
    const int g = lane >> 2, tg = lane & 3;
    const int wm = wid & 3, wn = wid >> 2;
    const int m0 = blockIdx.x * 128;

    unsigned* h1hi = smu;            // [128][132]
    unsigned* h1lo = smu + 16896;
    float*    zbuf = sm + 33792;     // 2 x [128][20]
    unsigned* w1h  = smu + 38912;    // 2 x [256][12]
    unsigned* w1l  = smu + 45056;

    // ================= GEMM1: h1 = relu(z @ W1^T + b1) =================
    float acc1[2][8][4];
    #pragma unroll
    for (int a = 0; a < 2; a++)
        #pragma unroll
        for (int b = 0; b < 8; b++)
            #pragma unroll
            for (int c = 0; c < 4; c++) acc1[a][b][c] = 0.f;

    auto stage1 = [&](int buf, int kc) {
        const int k0 = kc * 16;
        // z: 128 rows x 16 fp32, smem stride 20.
        // Row stride 361 floats is NOT 16B-aligned -> must use 4-byte cp.async.
        {
            int m = tid >> 2, q4 = (tid & 3) * 4;
            int gk = k0 + q4;
            float* dst = zbuf + buf * 2560 + m * 20 + q4;
            const float* src = z + (size_t)(m0 + m) * 361 + gk;
            #pragma unroll
            for (int j = 0; j < 4; j++) {
                if (gk + j < 361) cpa4(dst + j, src + j);
                else              dst[j] = 0.f;
            }
        }
        // W1 chunk: 256 rows x 8 u32, smem stride 12 (16B-aligned both sides)
        {
            int n = tid >> 1, q4 = (tid & 1) * 4;
            const unsigned* sh = g_W1h + kc * 2048 + n * 8 + q4;
            const unsigned* sl = g_W1l + kc * 2048 + n * 8 + q4;
            cpa16(w1h + buf * 3072 + n * 12 + q4, sh);
            cpa16(w1l + buf * 3072 + n * 12 + q4, sl);
        }
    };

    stage1(0, 0); cp_commit();
    for (int kc = 0; kc < NCH1; kc++) {
        if (kc + 1 < NCH1) { stage1((kc + 1) & 1, kc + 1); cp_commit(); cp_wait<1>(); }
        else               { cp_wait<0>(); }
        __syncthreads();
        const float* az = zbuf + (kc & 1) * 2560 + (wm * 32) * 20;
        const unsigned* bh = w1h + (kc & 1) * 3072;
        const unsigned* bl = w1l + (kc & 1) * 3072;
        unsigned Ah[2][4], Al[2][4];
        ldA_f32(az,            20, g, tg, Ah[0], Al[0]);
        ldA_f32(az + 16 * 20,  20, g, tg, Ah[1], Al[1]);
        #pragma unroll
        for (int nt = 0; nt < 8; nt++) {
            const unsigned* pb = bh + (wn * 64 + nt * 8 + g) * 12 + tg;
            const unsigned* pc = bl + (wn * 64 + nt * 8 + g) * 12 + tg;
            unsigned B0 = pb[0], B1 = pb[4], C0 = pc[0], C1 = pc[4];
            mma16(acc1[0][nt], Ah[0], B0, B1); mma16(acc1[1][nt], Ah[1], B0, B1);
            mma16(acc1[0][nt], Ah[0], C0, C1); mma16(acc1[1][nt], Ah[1], C0, C1);
            mma16(acc1[0][nt], Al[0], B0, B1); mma16(acc1[1][nt], Al[1], B0, B1);
        }
        __syncthreads();
    }

    // prefetch W2 chunk 0 (over dead z/W1 region)
    unsigned* w2h = smu + 33792;  // 2 x [128][36]
    unsigned* w2l = smu + 43008;
    auto stage2 = [&](int buf, int kc) {
        #pragma unroll
        for (int i = tid; i < 1024; i += 512) {
            int n = i >> 3, q4 = (i & 7) * 4;
            cpa16(w2h + buf * 4608 + n * 36 + q4, g_W2h + kc * 4096 + n * 32 + q4);
            cpa16(w2l + buf * 4608 + n * 36 + q4, g_W2l + kc * 4096 + n * 32 + q4);
        }
    };
    stage2(0, 0); cp_commit();

    // GEMM1 epilogue: h1 = relu(acc + b1) -> packed bf16 hi/lo [128][132]
    #pragma unroll
    for (int mt = 0; mt < 2; mt++) {
        #pragma unroll
        for (int nt = 0; nt < 8; nt++) {
            int m = wm * 32 + mt * 16 + g;
            int n = wn * 64 + nt * 8 + 2 * tg;
            int nu = n >> 1;
            float bv0 = __ldg(b1 + n), bv1 = __ldg(b1 + n + 1);
            unsigned hi, lo;
            split2(relu_(acc1[mt][nt][0] + bv0), relu_(acc1[mt][nt][1] + bv1), hi, lo);
            h1hi[m * 132 + nu] = hi; h1lo[m * 132 + nu] = lo;
            split2(relu_(acc1[mt][nt][2] + bv0), relu_(acc1[mt][nt][3] + bv1), hi, lo);
            h1hi[(m + 8) * 132 + nu] = hi; h1lo[(m + 8) * 132 + nu] = lo;
        }
    }
    __syncthreads();

    // ================= GEMM2: h2 = relu(h1 @ W2^T + b2) =================
    float acc2[2][4][4];
    #pragma unroll
    for (int a = 0; a < 2; a++)
        #pragma unroll
        for (int b = 0; b < 4; b++)
            #pragma unroll
            for (int c = 0; c < 4; c++) acc2[a][b][c] = 0.f;

    for (int kc = 0; kc < 4; kc++) {
        if (kc + 1 < 4) { stage2((kc + 1) & 1, kc + 1); cp_commit(); cp_wait<1>(); }
        else            { cp_wait<0>(); }
        __syncthreads();
        #pragma unroll
        for (int q = 0; q < 4; q++) {
            int u0 = kc * 32 + q * 8;
            unsigned Ah[2][4], Al[2][4];
            #pragma unroll
            for (int mt = 0; mt < 2; mt++) {
                int m = wm * 32 + mt * 16 + g;
                const unsigned* ph = h1hi + m * 132 + u0 + tg;
                const unsigned* pl = h1lo + m * 132 + u0 + tg;
                Ah[mt][0] = ph[0]; Ah[mt][1] = ph[8 * 132]; Ah[mt][2] = ph[4]; Ah[mt][3] = ph[8 * 132 + 4];
                Al[mt][0] = pl[0]; Al[mt][1] = pl[8 * 132]; Al[mt][2] = pl[4]; Al[mt][3] = pl[8 * 132 + 4];
            }
            #pragma unroll
            for (int nt = 0; nt < 4; nt++) {
                int n = wn * 32 + nt * 8 + g;
                const unsigned* pb = w2h + (kc & 1) * 4608 + n * 36 + q * 8 + tg;
                const unsigned* pc = w2l + (kc & 1) * 4608 + n * 36 + q * 8 + tg;
                unsigned B0 = pb[0], B1 = pb[4], C0 = pc[0], C1 = pc[4];
                mma16(acc2[0][nt], Ah[0], B0, B1); mma16(acc2[1][nt], Ah[1], B0, B1);
                mma16(acc2[0][nt], Ah[0], C0, C1); mma16(acc2[1][nt], Ah[1], C0, C1);
                mma16(acc2[0][nt], Al[0], B0, B1); mma16(acc2[1][nt], Al[1], B0, B1);
            }
        }
        __syncthreads();
    }

    // stage W3 (over dead h1 rows region @8704) while writing h2 epilogue
    unsigned* w3h = smu + 8704;   // [64][68]
    unsigned* w3l = smu + 13056;
    #pragma unroll
    for (int i = tid; i < 1024; i += 512) {
        int n = i >> 4, q4 = (i & 15) * 4;
        cpa16(w3h + n * 68 + q4, g_W3h + n * 64 + q4);
        cpa16(w3l + n * 68 + q4, g_W3l + n * 64 + q4);
    }
    cp_commit();

    unsigned* h2hi = smu + 33792;  // [128][68] (over dead W2 bufs)
    unsigned* h2lo = smu + 42496;
    #pragma unroll
    for (int mt = 0; mt < 2; mt++) {
        #pragma unroll
        for (int nt = 0; nt < 4; nt++) {
            int m = wm * 32 + mt * 16 + g;
            int n = wn * 32 + nt * 8 + 2 * tg;
            int nu = n >> 1;
            float bv0 = __ldg(b2 + n), bv1 = __ldg(b2 + n + 1);
            unsigned hi, lo;
            split2(relu_(acc2[mt][nt][0] + bv0), relu_(acc2[mt][nt][1] + bv1), hi, lo);
            h2hi[m * 68 + nu] = hi; h2lo[m * 68 + nu] = lo;
            split2(relu_(acc2[mt][nt][2] + bv0), relu_(acc2[mt][nt][3] + bv1), hi, lo);
            h2hi[(m + 8) * 68 + nu] = hi; h2lo[(m + 8) * 68 + nu] = lo;
        }
    }
    cp_wait<0>();
    __syncthreads();

    // ================= GEMM3: h = relu(h2 @ W3^T + b3) =================
    float acc3[2][2][4];
    #pragma unroll
    for (int a = 0; a < 2; a++)
        #pragma unroll
        for (int b = 0; b < 2; b++)
            #pragma unroll
            for (int c = 0; c < 4; c++) acc3[a][b][c] = 0.f;

    #pragma unroll
    for (int q = 0; q < 8; q++) {
        int u0 = q * 8;
        unsigned Ah[2][4], Al[2][4];
        #pragma unroll
        for (int mt = 0; mt < 2; mt++) {
            int m = wm * 32 + mt * 16 + g;
            const unsigned* ph = h2hi + m * 68 + u0 + tg;
            const unsigned* pl = h2lo + m * 68 + u0 + tg;
            Ah[mt][0] = ph[0]; Ah[mt][1] = ph[8 * 68]; Ah[mt][2] = ph[4]; Ah[mt][3] = ph[8 * 68 + 4];
            Al[mt][0] = pl[0]; Al[mt][1] = pl[8 * 68]; Al[mt][2] = pl[4]; Al[mt][3] = pl[8 * 68 + 4];
        }
        #pragma unroll
        for (int nt = 0; nt < 2; nt++) {
            int n = wn * 16 + nt * 8 + g;
            const unsigned* pb = w3h + n * 68 + u0 + tg;
            const unsigned* pc = w3l + n * 68 + u0 + tg;
            unsigned B0 = pb[0], B1 = pb[4], C0 = pc[0], C1 = pc[4];
            mma16(acc3[0][nt], Ah[0], B0, B1); mma16(acc3[1][nt], Ah[1], B0, B1);
            mma16(acc3[0][nt], Ah[0], C0, C1); mma16(acc3[1][nt], Ah[1], C0, C1);
            mma16(acc3[0][nt], Al[0], B0, B1); mma16(acc3[1][nt], Al[1], B0, B1);
        }
    }
    __syncthreads();

    // ================= GRU setup =================
    float*    h     = sm;                // [128][68] fp32
    float*    gh    = sm + 8704;         // [128][196]
    unsigned* whhh  = smu + 33792;       // [192][36]
    unsigned* whhl  = smu + 40704;
    float*    wih   = sm + 47616;        // [192][2]
    float*    sbih  = sm + 48000;
    float*    sbhh  = sm + 48192;
    float*    swo   = sm + 48384;
    float*    sbo   = sm + 48512;
    float*    x     = sm + 48516;        // [128][2]
    float*    xh    = sm + 48772;        // [128][20]

    // stage Whh (over dead h2) + small arrays
    #pragma unroll
    for (int i = tid; i < 1536; i += 512) {
        int n = i >> 3, q4 = (i & 7) * 4;
        cpa16(whhh + n * 36 + q4, g_Whh + n * 32 + q4);
        cpa16(whhl + n * 36 + q4, g_Whl + n * 32 + q4);
    }
    cp_commit();
    if (tid < 384) wih[tid] = Wih[tid];
    if (tid < 192) { sbih[tid] = bih[tid]; sbhh[tid] = bhh[tid]; }
    if (tid < 128) swo[tid] = Wo[tid];
    if (tid < 2)   sbo[tid] = bo[tid];
    if (tid < 256) x[tid] = 0.f;

    // GEMM3 epilogue: h = relu(acc + b3) fp32 @0 (h1 region dead)
    #pragma unroll
    for (int mt = 0; mt < 2; mt++) {
        #pragma unroll
        for (int nt = 0; nt < 2; nt++) {
            int m = wm * 32 + mt * 16 + g;
            int n = wn * 16 + nt * 8 + 2 * tg;
            float bv0 = __ldg(b3 + n), bv1 = __ldg(b3 + n + 1);
            h[m * 68 + n]           = relu_(acc3[mt][nt][0] + bv0);
            h[m * 68 + n + 1]       = relu_(acc3[mt][nt][1] + bv1);
            h[(m + 8) * 68 + n]     = relu_(acc3[mt][nt][2] + bv0);
            h[(m + 8) * 68 + n + 1] = relu_(acc3[mt][nt][3] + bv1);
        }
    }
    cp_wait<0>();
    __syncthreads();

    // ================= GRU loop =================
    for (int t = 0; t < PLEN; t++) {
        // gh = h @ Whh^T
        float acc[2][6][4];
        #pragma unroll
        for (int a = 0; a < 2; a++)
            #pragma unroll
            for (int b = 0; b < 6; b++)
                #pragma unroll
                for (int c = 0; c < 4; c++) acc[a][b][c] = 0.f;

        #pragma unroll
        for (int q = 0; q < 4; q++) {
            unsigned Ah[2][4], Al[2][4];
            ldA_f32(h + (wm * 32) * 68 + q * 16,           68, g, tg, Ah[0], Al[0]);
            ldA_f32(h + (wm * 32 + 16) * 68 + q * 16,      68, g, tg, Ah[1], Al[1]);
            #pragma unroll
            for (int nt = 0; nt < 6; nt++) {
                int n = wn * 48 + nt * 8 + g;
                const unsigned* pb = whhh + n * 36 + q * 8 + tg;
                const unsigned* pc = whhl + n * 36 + q * 8 + tg;
                unsigned B0 = pb[0], B1 = pb[4], C0 = pc[0], C1 = pc[4];
                mma16(acc[0][nt], Ah[0], B0, B1); mma16(acc[1][nt], Ah[1], B0, B1);
                mma16(acc[0][nt], Ah[0], C0, C1); mma16(acc[1][nt], Ah[1], C0, C1);
                mma16(acc[0][nt], Al[0], B0, B1); mma16(acc[1][nt], Al[1], B0, B1);
            }
        }
        #pragma unroll
        for (int mt = 0; mt < 2; mt++) {
            #pragma unroll
            for (int nt = 0; nt < 6; nt++) {
                int m = wm * 32 + mt * 16 + g;
                int n = wn * 48 + nt * 8 + 2 * tg;
                *(float2*)&gh[m * 196 + n]       = make_float2(acc[mt][nt][0], acc[mt][nt][1]);
                *(float2*)&gh[(m + 8) * 196 + n] = make_float2(acc[mt][nt][2], acc[mt][nt][3]);
            }
        }
        __syncthreads();

        // gates (exact fp32), in-place h update
        #pragma unroll
        for (int e = tid; e < 8192; e += 512) {
            int r = e >> 6, j = e & 63;
            float x0v = x[r * 2], x1v = x[r * 2 + 1];
            float ghr = gh[r * 196 + j]       + sbhh[j];
            float ghz = gh[r * 196 + j + 64]  + sbhh[j + 64];
            float ghn = gh[r * 196 + j + 128] + sbhh[j + 128];
            float gir = x0v * wih[j * 2]           + x1v * wih[j * 2 + 1]           + sbih[j];
            float giz = x0v * wih[(j + 64) * 2]    + x1v * wih[(j + 64) * 2 + 1]    + sbih[j + 64];
            float gin = x0v * wih[(j + 128) * 2]   + x1v * wih[(j + 128) * 2 + 1]   + sbih[j + 128];
            float rg = __fdividef(1.f, 1.f + __expf(-(gir + ghr)));
            float zg = __fdividef(1.f, 1.f + __expf(-(giz + ghz)));
            float av = gin + rg * ghn;
            float e2 = __expf(2.f * fabsf(av));
            float tv = 1.f - __fdividef(2.f, e2 + 1.f);
            float ng = copysignf(tv, av);
            float hv = h[r * 68 + j];
            h[r * 68 + j] = (1.f - zg) * ng + zg * hv;
        }
        __syncthreads();

        // dx = h_new @ Wo^T + bo ; x += dx
        if (tid < 256) {
            int r = tid >> 1, o = tid & 1;
            float s = sbo[o];
            const float* hr = h + r * 68;
            const float* wr = swo + o * 64;
            #pragma unroll 8
            for (int j = 0; j < 64; j++) s += hr[j] * wr[j];
            float xv = x[r * 2 + o] + s;
            x[r * 2 + o] = xv;
            xh[r * 20 + t * 2 + o] = xv;
        }
        __syncthreads();
    }

    // coalesced output: out[b, t, o]
    #pragma unroll
    for (int i = tid; i < 640; i += 512) {
        int r = i / 5, q = (i % 5) * 4;
        *(float4*)&out[(size_t)(m0 + r) * 20 + q] = *(const float4*)&xh[r * 20 + q];
    }
}

// ---------------------------------------------------------------------------
extern "C" void kernel_launch(void* const* d_in, const int* in_sizes, int n_in,
                              void* d_out, int out_size)
{
    const float* z   = (const float*)d_in[0];
    const float* W1  = (const float*)d_in[1];
    const float* b1  = (const float*)d_in[2];
    const float* W2  = (const float*)d_in[3];
    const float* b2  = (const float*)d_in[4];
    const float* W3  = (const float*)d_in[5];
    const float* b3  = (const float*)d_in[6];
    const float* Wih = (const float*)d_in[7];
    const float* Whh = (const float*)d_in[8];
    const float* bih = (const float*)d_in[9];
    const float* bhh = (const float*)d_in[10];
    const float* Wo  = (const float*)d_in[11];
    const float* bo  = (const float*)d_in[12];
    float* out = (float*)d_out;

    const int smem = 52224 * 4;  // 208896 B
    cudaFuncSetAttribute(fused_kernel, cudaFuncAttributeMaxDynamicSharedMemorySize, smem);

    prep_kernel<<<288, 256>>>(W1, W2, W3, Whh);
    fused_kernel<<<BS / 128, 512, smem>>>(z, b1, b2, b3, Wih, bih, bhh, Wo, bo, out);
}